// round 3
// baseline (speedup 1.0000x reference)
#include <cuda_runtime.h>
#include <cuda_bf16.h>

#define PROPOSALS_PER_IM 300
#define HUBER_T 3.0f
#define THREADS 256
#define ITEMS 4
#define MAX_BLOCKS 1024

__device__ float        g_partial[MAX_BLOCKS];
__device__ unsigned int g_count = 0;

__device__ __forceinline__ float huber1(float d) {
    float a = fabsf(d);
    return (a < HUBER_T) ? d * d : a;
}

__device__ __forceinline__ float huber4(float4 p, float4 g) {
    return huber1(p.x - g.x) + huber1(p.y - g.y) +
           huber1(p.z - g.z) + huber1(p.w - g.w);
}

__global__ void __launch_bounds__(THREADS)
_RPN_71459665871443_kernel(const float* __restrict__ out8,
                           const float* __restrict__ gt,
                           const int* __restrict__ cp,
                           float* __restrict__ d_out,
                           int B, float inv_n) {
    const int t = blockIdx.x * blockDim.x + threadIdx.x;
    const int b0 = t * ITEMS;
    float s = 0.0f;

    if (b0 + ITEMS - 1 < B) {
        // vector path: 1x int4 + 4x float4 gt (coalesced) + 4x independent gathers
        int4 c = *reinterpret_cast<const int4*>(cp + b0);
        const float4* gt4 = reinterpret_cast<const float4*>(gt) + b0;
        float4 g0 = gt4[0], g1 = gt4[1], g2 = gt4[2], g3 = gt4[3];
        // row stride 8 floats, pred_box = cols [4..8): byte off = idx*32+16 (16B aligned)
        long long i0 = (long long)c.x + (long long)PROPOSALS_PER_IM * (b0 + 0);
        long long i1 = (long long)c.y + (long long)PROPOSALS_PER_IM * (b0 + 1);
        long long i2 = (long long)c.z + (long long)PROPOSALS_PER_IM * (b0 + 2);
        long long i3 = (long long)c.w + (long long)PROPOSALS_PER_IM * (b0 + 3);
        float4 p0 = *reinterpret_cast<const float4*>(out8 + i0 * 8 + 4);
        float4 p1 = *reinterpret_cast<const float4*>(out8 + i1 * 8 + 4);
        float4 p2 = *reinterpret_cast<const float4*>(out8 + i2 * 8 + 4);
        float4 p3 = *reinterpret_cast<const float4*>(out8 + i3 * 8 + 4);
        s = huber4(p0, g0) + huber4(p1, g1) + huber4(p2, g2) + huber4(p3, g3);
    } else {
        for (int b = b0; b < B && b < b0 + ITEMS; b++) {
            long long idx = (long long)cp[b] + (long long)PROPOSALS_PER_IM * b;
            float4 p = *reinterpret_cast<const float4*>(out8 + idx * 8 + 4);
            float4 g = *reinterpret_cast<const float4*>(gt + 4LL * b);
            s += huber4(p, g);
        }
    }

    // warp reduction
    #pragma unroll
    for (int off = 16; off > 0; off >>= 1)
        s += __shfl_down_sync(0xFFFFFFFFu, s, off);

    __shared__ float warp_sums[THREADS / 32];
    __shared__ bool  is_last;
    int lane = threadIdx.x & 31;
    int wid  = threadIdx.x >> 5;
    if (lane == 0) warp_sums[wid] = s;
    __syncthreads();
    if (wid == 0) {
        s = (lane < (THREADS / 32)) ? warp_sums[lane] : 0.0f;
        #pragma unroll
        for (int off = 4; off > 0; off >>= 1)
            s += __shfl_down_sync(0xFFFFFFFFu, s, off);
        if (lane == 0) {
            g_partial[blockIdx.x] = s;
            __threadfence();
            unsigned int done = atomicInc(&g_count, gridDim.x - 1);
            is_last = (done == gridDim.x - 1);
        }
    }
    __syncthreads();

    // last block to finish reduces the partials and writes the scalar result
    if (is_last) {
        float tot = 0.0f;
        for (int i = threadIdx.x; i < (int)gridDim.x; i += blockDim.x) {
            // partials of other blocks: read through L2 (bypass L1, no stale data)
            tot += __ldcg(&g_partial[i]);
        }
        #pragma unroll
        for (int off = 16; off > 0; off >>= 1)
            tot += __shfl_down_sync(0xFFFFFFFFu, tot, off);
        if (lane == 0) warp_sums[wid] = tot;
        __syncthreads();
        if (wid == 0) {
            tot = (lane < (THREADS / 32)) ? warp_sums[lane] : 0.0f;
            #pragma unroll
            for (int off = 4; off > 0; off >>= 1)
                tot += __shfl_down_sync(0xFFFFFFFFu, tot, off);
            if (lane == 0) {
                d_out[0] = tot * inv_n;
                g_count = 0;  // reset for next graph replay (deterministic)
            }
        }
    }
}

extern "C" void kernel_launch(void* const* d_in, const int* in_sizes, int n_in,
                              void* d_out, int out_size) {
    // Identify inputs by element count (order-proof):
    //   output: B*300*8 (largest), central_pos: B (smallest), gt_boxes: B*4
    int i_out = 0, i_cp = 0;
    for (int i = 1; i < n_in; i++) {
        if (in_sizes[i] > in_sizes[i_out]) i_out = i;
        if (in_sizes[i] < in_sizes[i_cp])  i_cp  = i;
    }
    int i_gt = 0;
    for (int i = 0; i < n_in; i++)
        if (i != i_out && i != i_cp) { i_gt = i; break; }

    const float* out8 = (const float*)d_in[i_out];
    const float* gt   = (const float*)d_in[i_gt];
    const int*   cp   = (const int*)d_in[i_cp];

    int B = in_sizes[i_cp];
    float inv_n = 1.0f / (4.0f * (float)B);

    int blocks = (B + THREADS * ITEMS - 1) / (THREADS * ITEMS);
    if (blocks > MAX_BLOCKS) blocks = MAX_BLOCKS;  // B<=1024*1024 covered; here B=65536 -> 64
    _RPN_71459665871443_kernel<<<blocks, THREADS>>>(out8, gt, cp, (float*)d_out, B, inv_n);
}

// round 4
// speedup vs baseline: 1.0551x; 1.0551x over previous
#include <cuda_runtime.h>
#include <cuda_bf16.h>

#define PROPOSALS_PER_IM 300
#define HUBER_T 3.0f
#define THREADS 64
#define ITEMS 4
#define MAX_BLOCKS 1024

__device__ float g_partial[MAX_BLOCKS];

__device__ __forceinline__ float huber1(float d) {
    float a = fabsf(d);
    return (a < HUBER_T) ? d * d : a;
}

__device__ __forceinline__ float huber4(float4 p, float4 g) {
    return huber1(p.x - g.x) + huber1(p.y - g.y) +
           huber1(p.z - g.z) + huber1(p.w - g.w);
}

__global__ void __launch_bounds__(THREADS)
_RPN_71459665871443_main(const float* __restrict__ out8,
                         const float* __restrict__ gt,
                         const int* __restrict__ cp,
                         int B) {
    float s = 0.0f;
    const int stride = gridDim.x * blockDim.x;  // threads in grid

    // grid-stride at ITEMS granularity (one pass for B=65536 with 256x64)
    for (int base = (blockIdx.x * blockDim.x + threadIdx.x) * ITEMS;
         base < B; base += stride * ITEMS) {
        if (base + ITEMS - 1 < B) {
            int4 c = *reinterpret_cast<const int4*>(cp + base);
            const float4* gt4 = reinterpret_cast<const float4*>(gt) + base;
            float4 g0 = gt4[0], g1 = gt4[1], g2 = gt4[2], g3 = gt4[3];
            long long i0 = (long long)c.x + (long long)PROPOSALS_PER_IM * (base + 0);
            long long i1 = (long long)c.y + (long long)PROPOSALS_PER_IM * (base + 1);
            long long i2 = (long long)c.z + (long long)PROPOSALS_PER_IM * (base + 2);
            long long i3 = (long long)c.w + (long long)PROPOSALS_PER_IM * (base + 3);
            // pred_box = cols [4..8): byte offset idx*32+16, 16B-aligned float4
            float4 p0 = *reinterpret_cast<const float4*>(out8 + i0 * 8 + 4);
            float4 p1 = *reinterpret_cast<const float4*>(out8 + i1 * 8 + 4);
            float4 p2 = *reinterpret_cast<const float4*>(out8 + i2 * 8 + 4);
            float4 p3 = *reinterpret_cast<const float4*>(out8 + i3 * 8 + 4);
            s += huber4(p0, g0) + huber4(p1, g1) + huber4(p2, g2) + huber4(p3, g3);
        } else {
            for (int b = base; b < B; b++) {
                long long idx = (long long)cp[b] + (long long)PROPOSALS_PER_IM * b;
                float4 p = *reinterpret_cast<const float4*>(out8 + idx * 8 + 4);
                float4 g = *reinterpret_cast<const float4*>(gt + 4LL * b);
                s += huber4(p, g);
            }
        }
    }

    // warp reduction
    #pragma unroll
    for (int off = 16; off > 0; off >>= 1)
        s += __shfl_down_sync(0xFFFFFFFFu, s, off);

    __shared__ float warp_sums[THREADS / 32];
    int lane = threadIdx.x & 31;
    int wid  = threadIdx.x >> 5;
    if (lane == 0) warp_sums[wid] = s;
    __syncthreads();
    if (threadIdx.x == 0) {
        float t = warp_sums[0];
        #pragma unroll
        for (int w = 1; w < THREADS / 32; w++) t += warp_sums[w];
        g_partial[blockIdx.x] = t;
    }
}

__global__ void __launch_bounds__(256)
_RPN_71459665871443_reduce(float* __restrict__ d_out, int nblocks, float inv_n) {
    float s = 0.0f;
    for (int i = threadIdx.x; i < nblocks; i += blockDim.x)
        s += g_partial[i];
    #pragma unroll
    for (int off = 16; off > 0; off >>= 1)
        s += __shfl_down_sync(0xFFFFFFFFu, s, off);

    __shared__ float warp_sums[8];
    int lane = threadIdx.x & 31;
    int wid  = threadIdx.x >> 5;
    if (lane == 0) warp_sums[wid] = s;
    __syncthreads();
    if (threadIdx.x == 0) {
        float t = warp_sums[0];
        #pragma unroll
        for (int w = 1; w < 8; w++) t += warp_sums[w];
        d_out[0] = t * inv_n;
    }
}

extern "C" void kernel_launch(void* const* d_in, const int* in_sizes, int n_in,
                              void* d_out, int out_size) {
    // Identify inputs by element count (order-proof):
    //   output: B*300*8 (largest), central_pos: B (smallest), gt_boxes: B*4
    int i_out = 0, i_cp = 0;
    for (int i = 1; i < n_in; i++) {
        if (in_sizes[i] > in_sizes[i_out]) i_out = i;
        if (in_sizes[i] < in_sizes[i_cp])  i_cp  = i;
    }
    int i_gt = 0;
    for (int i = 0; i < n_in; i++)
        if (i != i_out && i != i_cp) { i_gt = i; break; }

    const float* out8 = (const float*)d_in[i_out];
    const float* gt   = (const float*)d_in[i_gt];
    const int*   cp   = (const int*)d_in[i_cp];

    int B = in_sizes[i_cp];
    float inv_n = 1.0f / (4.0f * (float)B);

    int blocks = (B + THREADS * ITEMS - 1) / (THREADS * ITEMS);
    if (blocks > MAX_BLOCKS) blocks = MAX_BLOCKS;  // grid-stride loop covers the rest
    _RPN_71459665871443_main<<<blocks, THREADS>>>(out8, gt, cp, B);
    _RPN_71459665871443_reduce<<<1, 256>>>((float*)d_out, blocks, inv_n);
}